// round 15
// baseline (speedup 1.0000x reference)
#include <cuda_runtime.h>
#include <cuda_bf16.h>
#include <math.h>
#include <stdint.h>

#define VOCAB   32000
#define EMBED   300
#define KPAD    304
#define HIDDEN  1024
#define BATCH   64
#define SEQLEN  512
#define GDIM    4096

#define NCTA2   128
#define TPB2    1024

#define ESZ     (VOCAB * KPAD)
#define WSZ     (GDIM * KPAD)

// ---------------- device scratch ----------------
__device__ float          g_xz[(size_t)SEQLEN * BATCH * GDIM];
__device__ __nv_bfloat16  g_esplit[2 * ESZ];
__device__ __nv_bfloat16  g_wsplit[2 * WSZ];
__device__ __nv_bfloat16  g_hsplit[2][2 * 64 * 1024];
__device__ __nv_bfloat16  g_Rsplit[(size_t)NCTA2 * 32 * 2048];
__device__ unsigned       g_bar_count;
__device__ volatile unsigned g_bar_gen;

// ---------------- grid barrier ----------------
__device__ __forceinline__ void grid_barrier() {
    __syncthreads();
    if (threadIdx.x == 0) {
        __threadfence();
        unsigned g = g_bar_gen;
        if (atomicAdd(&g_bar_count, 1u) == NCTA2 - 1u) {
            atomicExch(&g_bar_count, 0u);
            __threadfence();
            g_bar_gen = g + 1u;
        } else {
            while (g_bar_gen == g) { }
        }
        __threadfence();
    }
    __syncthreads();
}

__device__ __forceinline__ void mma16816(float* d,
                                         uint32_t a0, uint32_t a1, uint32_t a2, uint32_t a3,
                                         uint32_t b0, uint32_t b1) {
    asm volatile("mma.sync.aligned.m16n8k16.row.col.f32.bf16.bf16.f32 "
        "{%0,%1,%2,%3}, {%4,%5,%6,%7}, {%8,%9}, {%0,%1,%2,%3};"
        : "+f"(d[0]), "+f"(d[1]), "+f"(d[2]), "+f"(d[3])
        : "r"(a0), "r"(a1), "r"(a2), "r"(a3), "r"(b0), "r"(b1));
}
__device__ __forceinline__ void ldsm4(uint32_t& r0, uint32_t& r1, uint32_t& r2, uint32_t& r3,
                                      uint32_t addr) {
    asm volatile("ldmatrix.sync.aligned.m8n8.x4.shared.b16 {%0,%1,%2,%3}, [%4];"
        : "=r"(r0), "=r"(r1), "=r"(r2), "=r"(r3) : "r"(addr));
}
__device__ __forceinline__ void cp16(uint32_t dst, const void* src) {
    asm volatile("cp.async.cg.shared.global [%0], [%1], 16;" :: "r"(dst), "l"(src));
}
#define CP_COMMIT() asm volatile("cp.async.commit_group;" ::: "memory")
#define CP_WAIT0()  asm volatile("cp.async.wait_group 0;" ::: "memory")
#define NBAR(id)    asm volatile("bar.sync %0, 128;" :: "r"(id) : "memory")

__device__ __forceinline__ uint32_t smem_to_u32(const void* p) {
    uint32_t a;
    asm("{ .reg .u64 t; cvta.to.shared.u64 t, %1; cvt.u32.u64 %0, t; }" : "=r"(a) : "l"(p));
    return a;
}

// =========================================================================
// Prologues
// =========================================================================
__global__ void hinit_kernel() {
    uint4 z = make_uint4(0, 0, 0, 0);
    int n4 = 2 * 2 * 64 * 1024 / 8;
    for (int i = blockIdx.x * blockDim.x + threadIdx.x; i < n4; i += gridDim.x * blockDim.x)
        ((uint4*)g_hsplit)[i] = z;
}

__global__ void esplit_kernel(const float* __restrict__ emb) {
    size_t i = (size_t)blockIdx.x * blockDim.x + threadIdx.x;
    if (i >= (size_t)ESZ) return;
    int k   = (int)(i % KPAD);
    int row = (int)(i / KPAD);
    float x = (k < EMBED) ? emb[(size_t)row * EMBED + k] : 0.f;
    __nv_bfloat16 hi = __float2bfloat16(x);
    g_esplit[i]       = hi;
    g_esplit[ESZ + i] = __float2bfloat16(x - __bfloat162float(hi));
}

__global__ void wsplit_kernel(const float* __restrict__ W) {
    size_t i = (size_t)blockIdx.x * blockDim.x + threadIdx.x;
    if (i >= (size_t)WSZ) return;
    int k = (int)(i % KPAD);
    int n = (int)(i / KPAD);
    float x = (k < EMBED) ? W[(size_t)k * GDIM + n] : 0.f;
    __nv_bfloat16 hi = __float2bfloat16(x);
    g_wsplit[i]       = hi;
    g_wsplit[WSZ + i] = __float2bfloat16(x - __bfloat162float(hi));
}

__global__ void rsplit_kernel(const float* __restrict__ Rm) {
    size_t i = (size_t)blockIdx.x * blockDim.x + threadIdx.x;
    if (i >= (size_t)NCTA2 * 32 * 2048) return;
    int k   = (int)(i & 2047);
    int n   = (int)((i >> 11) & 31);
    int cta = (int)(i >> 16);
    int col = (n >> 3) * 1024 + cta * 8 + (n & 7);
    int ks  = k & 1023;
    float x = Rm[(size_t)ks * GDIM + col];
    __nv_bfloat16 hi = __float2bfloat16(x);
    g_Rsplit[i] = (k < 1024) ? hi : __float2bfloat16(x - __bfloat162float(hi));
}

// =========================================================================
// Phase 1 (unchanged R14 winner): xz = emb[seq] @ W + bias on mma.sync
// =========================================================================
#define P1T     256
#define A_PL    (64 * 24)
#define W_PL    (128 * 24)

__global__ void __launch_bounds__(P1T) xz_mma_kernel(
    const float* __restrict__ bias, const int* __restrict__ seq)
{
    __shared__ __align__(16) __nv_bfloat16 Asm[2][2][A_PL];
    __shared__ __align__(16) __nv_bfloat16 Wsm[2][2][W_PL];
    __shared__ int toks[64];

    const int tid  = threadIdx.x;
    const int wid  = tid >> 5;
    const int lane = tid & 31;
    const int n0   = blockIdx.x * 128;
    const int m0   = blockIdx.y * 64;
    const int mt   = wid & 3;
    const int ntw  = (wid >> 2) & 1;

    if (tid < 64) {
        int m = m0 + tid;
        toks[tid] = seq[(m & 63) * SEQLEN + (m >> 6)];
    }
    __syncthreads();

    const uint32_t sbA0 = smem_to_u32(&Asm[0][0][0]);
    const uint32_t sbW0 = smem_to_u32(&Wsm[0][0][0]);
    const uint32_t ABUFB = 2 * A_PL * 2;
    const uint32_t WBUFB = 2 * W_PL * 2;

    const int aRowL = (lane & 7) + ((lane >> 3) & 1) * 8;
    const int aK8   = ((lane >> 4) & 1) * 8;
    const int bRowL = (lane & 7) + ((lane >> 4) & 1) * 8;
    const int bK8   = ((lane >> 3) & 1) * 8;
    const uint32_t aBase = sbA0 + (mt * 16 + aRowL) * 48 + aK8 * 2;
    const uint32_t wBase = sbW0 + (ntw * 64 + bRowL) * 48 + bK8 * 2;

    float acc[4][8];
    #pragma unroll
    for (int q = 0; q < 4; q++)
        #pragma unroll
        for (int i = 0; i < 8; i++) acc[q][i] = 0.f;

    {
        int u = tid;
        int pl = u >> 7, r = (u >> 1) & 63, c = u & 1;
        cp16(sbA0 + pl * (A_PL * 2) + r * 48 + c * 16,
             g_esplit + (size_t)pl * ESZ + (size_t)toks[r] * KPAD + c * 8);
        #pragma unroll
        for (int pass = 0; pass < 2; pass++) {
            int v = pass * P1T + tid;
            int wpl = v >> 8, wr = (v >> 1) & 127, wc = v & 1;
            cp16(sbW0 + wpl * (W_PL * 2) + wr * 48 + wc * 16,
                 g_wsplit + (size_t)wpl * WSZ + (size_t)(n0 + wr) * KPAD + wc * 8);
        }
        CP_COMMIT();
    }

    for (int s = 0; s < 19; s++) {
        CP_WAIT0();
        __syncthreads();
        if (s < 18) {
            const int k0 = (s + 1) * 16;
            const uint32_t ab = sbA0 + ((s + 1) & 1) * ABUFB;
            const uint32_t wb = sbW0 + ((s + 1) & 1) * WBUFB;
            int u = tid;
            int pl = u >> 7, r = (u >> 1) & 63, c = u & 1;
            cp16(ab + pl * (A_PL * 2) + r * 48 + c * 16,
                 g_esplit + (size_t)pl * ESZ + (size_t)toks[r] * KPAD + k0 + c * 8);
            #pragma unroll
            for (int pass = 0; pass < 2; pass++) {
                int v = pass * P1T + tid;
                int wpl = v >> 8, wr = (v >> 1) & 127, wc = v & 1;
                cp16(wb + wpl * (W_PL * 2) + wr * 48 + wc * 16,
                     g_wsplit + (size_t)wpl * WSZ + (size_t)(n0 + wr) * KPAD + k0 + wc * 8);
            }
            CP_COMMIT();
        }

        const uint32_t aB = aBase + (s & 1) * ABUFB;
        const uint32_t wB = wBase + (s & 1) * WBUFB;
        uint32_t ah0, ah1, ah2, ah3, al0, al1, al2, al3;
        ldsm4(ah0, ah1, ah2, ah3, aB);
        ldsm4(al0, al1, al2, al3, aB + A_PL * 2);
        #pragma unroll
        for (int q = 0; q < 4; q++) {
            uint32_t b0, b1, b2, b3;
            ldsm4(b0, b1, b2, b3, wB + q * 16 * 48);
            mma16816(acc[q],     ah0, ah1, ah2, ah3, b0, b1);
            mma16816(acc[q] + 4, ah0, ah1, ah2, ah3, b2, b3);
            mma16816(acc[q],     al0, al1, al2, al3, b0, b1);
            mma16816(acc[q] + 4, al0, al1, al2, al3, b2, b3);
            ldsm4(b0, b1, b2, b3, wB + W_PL * 2 + q * 16 * 48);
            mma16816(acc[q],     ah0, ah1, ah2, ah3, b0, b1);
            mma16816(acc[q] + 4, ah0, ah1, ah2, ah3, b2, b3);
        }
        __syncthreads();
    }

    {
        const int fg = lane >> 2, ft = lane & 3;
        const int row1 = m0 + mt * 16 + fg;
        #pragma unroll
        for (int q = 0; q < 4; q++) {
            #pragma unroll
            for (int pr = 0; pr < 2; pr++) {
                int col = n0 + ntw * 64 + q * 16 + pr * 8 + 2 * ft;
                float bx = __ldg(&bias[col]);
                float by = __ldg(&bias[col + 1]);
                *(float2*)&g_xz[(size_t)row1 * GDIM + col] =
                    make_float2(acc[q][pr * 4 + 0] + bx, acc[q][pr * 4 + 1] + by);
                *(float2*)&g_xz[(size_t)(row1 + 8) * GDIM + col] =
                    make_float2(acc[q][pr * 4 + 2] + bx, acc[q][pr * 4 + 3] + by);
            }
        }
    }
}

// =========================================================================
// Phase 2 v5: 1024 threads / 32 warps (8 per SMSP).
// Warp: mt = wid&3 (m16), ntile = (wid>>2)&1 (n16), kq = wid>>3 (k-quarter).
// Group (mt,kq): 2 warps share a private chunk double-buffer (16r x 64k).
// Named barriers pair kq-siblings (4 warps / 128 thr, ids 1..8).
// z: 2 buffers (kq01 -> z0, kq23 -> z1) via smem atomicAdd; gate threads
// read-then-zero their slots (ordering via syncthreads + grid barrier).
// =========================================================================
// smem layout (bytes)
#define SM_B     0          // 32 x 4112                    = 131,584
#define BSTR_B   4112
#define SM_A     131584     // 16 grp x 2 buf x 2304        = 73,728
#define AGRP     4608
#define ABUFSZ   2304
#define ASTR_B   144        // 72 halves (16B-aligned rows, conflict-free)
#define SM_Z     205312     // 2 x 8448                     = 16,896
#define SMEM2    222208

__global__ void __launch_bounds__(TPB2, 1)
lstm_mma_kernel(const int* __restrict__ seq, float* __restrict__ out)
{
    extern __shared__ char smem[];
    const uint32_t sb = smem_to_u32(smem);
    const int tid   = threadIdx.x;
    const int wid   = tid >> 5;
    const int lane  = tid & 31;
    const int cta   = blockIdx.x;
    const int mt    = wid & 3;
    const int ntile = (wid >> 2) & 1;
    const int kq    = wid >> 3;                // 0..3
    const int grp   = mt * 4 + kq;             // 0..15
    const int nbid  = 1 + mt * 2 + (kq >> 1);  // 1..8, 128 threads each
    const int m0    = mt * 16;
    const int nbase = ntile * 16;
    const int kqof  = kq * 256;                // k offset of my quarter

    // ---- load resident B slice ----
    {
        const uint4* src = (const uint4*)(g_Rsplit + (size_t)cta * 32 * 2048);
        for (int idx = tid; idx < 32 * 256; idx += TPB2) {
            int r = idx >> 8, c = idx & 255;
            *(uint4*)(smem + SM_B + r * BSTR_B + c * 16) = src[r * 256 + c];
        }
    }
    // ---- zero z buffers ----
    for (int idx = tid; idx < 2 * 64 * 33; idx += TPB2)
        ((float*)(smem + SM_Z))[idx] = 0.f;

    // gate ownership (tid < 512): b = tid>>3, j = tid&7
    const int gb = (tid & 511) >> 3;
    const int gj = tid & 7;
    float c_r = 0.f, h_r = 0.f;

    // ldmatrix lane address components
    const int aRowL = (lane & 7) + ((lane >> 3) & 1) * 8;
    const int aK8   = ((lane >> 4) & 1) * 8;
    const int bRow  = nbase + (lane & 7) + ((lane >> 4) & 1) * 8;
    const int bK8   = ((lane >> 3) & 1) * 8;
    const uint32_t aAddr0  = sb + SM_A + grp * AGRP + aRowL * ASTR_B + aK8 * 2;
    const uint32_t bAddr0  = sb + SM_B + bRow * BSTR_B + bK8 * 2;
    const uint32_t aStage0 = sb + SM_A + grp * AGRP;

    float* z0_s = (float*)(smem + SM_Z);
    float* z1_s = (float*)(smem + SM_Z + 8448);
    float* zw_s = (kq < 2) ? z0_s : z1_s;

    grid_barrier();

    int p = 0;
    for (int t = 0; t < SEQLEN; t++) {
        const __nv_bfloat16* hbase = g_hsplit[p];

        // gate-input prefetch (tid<512), hidden under MMA phase
        float xi = 0.f, xf = 0.f, xg = 0.f, xo = 0.f;
        int mv = 0;
        if (tid < 512) {
            const float* xzr = g_xz + (size_t)t * (BATCH * GDIM) + (size_t)gb * GDIM + cta * 8 + gj;
            xi = __ldcg(xzr);
            xf = __ldcg(xzr + 1024);
            xg = __ldcg(xzr + 2048);
            xo = __ldcg(xzr + 3072);
            mv = __ldg(&seq[gb * SEQLEN + t]);
        }

        float acc[8];
        #pragma unroll
        for (int i = 0; i < 8; i++) acc[i] = 0.f;

        // stage chunk 0 (hi plane, k = kqof) into buf 0
        {
            #pragma unroll
            for (int pass = 0; pass < 2; pass++) {
                int u = pass * 64 + ntile * 32 + lane;
                int r = u >> 3, c = u & 7;
                cp16(aStage0 + r * ASTR_B + c * 16,
                     hbase + (size_t)(m0 + r) * 1024 + kqof + c * 8);
            }
            CP_COMMIT();
        }

        for (int ci = 0; ci < 8; ci++) {
            CP_WAIT0();
            NBAR(nbid);
            if (ci < 7) {
                int cn = ci + 1;
                const __nv_bfloat16* pl = hbase + (cn < 4 ? 0 : 65536);
                const int k0g = kqof + (cn & 3) * 64;
                const uint32_t dst = aStage0 + (cn & 1) * ABUFSZ;
                #pragma unroll
                for (int pass = 0; pass < 2; pass++) {
                    int u = pass * 64 + ntile * 32 + lane;
                    int r = u >> 3, c = u & 7;
                    cp16(dst + r * ASTR_B + c * 16,
                         pl + (size_t)(m0 + r) * 1024 + k0g + c * 8);
                }
                CP_COMMIT();
            }

            const uint32_t aB = aAddr0 + (ci & 1) * ABUFSZ;
            const int k0 = kqof + (ci & 3) * 64;
            const bool isHi = (ci < 4);
            #pragma unroll
            for (int ks = 0; ks < 4; ks++) {
                const int kl = ks * 16;
                uint32_t a0, a1, a2, a3, b0, b1, b2, b3;
                ldsm4(a0, a1, a2, a3, aB + kl * 2);
                ldsm4(b0, b1, b2, b3, bAddr0 + (k0 + kl) * 2);
                mma16816(acc,     a0, a1, a2, a3, b0, b1);
                mma16816(acc + 4, a0, a1, a2, a3, b2, b3);
                if (isHi) {
                    ldsm4(b0, b1, b2, b3, bAddr0 + (1024 + k0 + kl) * 2);
                    mma16816(acc,     a0, a1, a2, a3, b0, b1);
                    mma16816(acc + 4, a0, a1, a2, a3, b2, b3);
                }
            }
        }

        // ---- park z via smem atomicAdd (2 writer-war至 per slot per buffer) ----
        {
            const int fg = lane >> 2, ft = lane & 3;
            #pragma unroll
            for (int blk = 0; blk < 2; blk++) {
                int ncol = nbase + blk * 8 + 2 * ft;
                atomicAdd(&zw_s[(m0 + fg)     * 33 + ncol],     acc[blk * 4 + 0]);
                atomicAdd(&zw_s[(m0 + fg)     * 33 + ncol + 1], acc[blk * 4 + 1]);
                atomicAdd(&zw_s[(m0 + fg + 8) * 33 + ncol],     acc[blk * 4 + 2]);
                atomicAdd(&zw_s[(m0 + fg + 8) * 33 + ncol + 1], acc[blk * 4 + 3]);
            }
        }
        __syncthreads();

        // ---- gates (tid < 512): thread owns (b=gb, j = cta*8 + gj) ----
        if (tid < 512) {
            const bool msk = (mv != 0);
            const int  zb  = gb * 33 + gj;
            float zi = z0_s[zb]      + z1_s[zb]      + xi;
            float zf = z0_s[zb + 8]  + z1_s[zb + 8]  + xf;
            float zg = z0_s[zb + 16] + z1_s[zb + 16] + xg;
            float zo = z0_s[zb + 24] + z1_s[zb + 24] + xo;
            // read-then-zero (next step's atomics ordered by grid barrier)
            z0_s[zb] = 0.f;      z1_s[zb] = 0.f;
            z0_s[zb + 8] = 0.f;  z1_s[zb + 8] = 0.f;
            z0_s[zb + 16] = 0.f; z1_s[zb + 16] = 0.f;
            z0_s[zb + 24] = 0.f; z1_s[zb + 24] = 0.f;

            float ig  = 1.f / (1.f + __expf(-zi));
            float fgt = 1.f / (1.f + __expf(-zf));
            float gg  = tanhf(zg);
            float og  = 1.f / (1.f + __expf(-zo));
            float cn = fgt * c_r + ig * gg;
            float hn = og * tanhf(cn);
            if (msk) { c_r = cn; h_r = hn; }

            __nv_bfloat16 hi = __float2bfloat16(h_r);
            __nv_bfloat16 lo = __float2bfloat16(h_r - __bfloat162float(hi));
            __nv_bfloat16* hN = g_hsplit[p ^ 1];
            hN[(size_t)gb * 1024 + cta * 8 + gj]         = hi;
            hN[65536 + (size_t)gb * 1024 + cta * 8 + gj] = lo;
        }

        p ^= 1;
        grid_barrier();
    }

    if (tid < 512)
        out[(size_t)gb * HIDDEN + cta * 8 + gj] = h_r;
}

// ---------------- launch ----------------
extern "C" void kernel_launch(void* const* d_in, const int* in_sizes, int n_in,
                              void* d_out, int out_size) {
    const float* emb  = nullptr;
    const float* W    = nullptr;
    const float* Rm   = nullptr;
    const float* bias = nullptr;
    const int*   seq  = nullptr;
    for (int i = 0; i < n_in; i++) {
        switch (in_sizes[i]) {
            case VOCAB * EMBED:  emb  = (const float*)d_in[i]; break;
            case EMBED * GDIM:   W    = (const float*)d_in[i]; break;
            case HIDDEN * GDIM:  Rm   = (const float*)d_in[i]; break;
            case GDIM:           bias = (const float*)d_in[i]; break;
            case BATCH * SEQLEN: seq  = (const int*)d_in[i];   break;
        }
    }
    (void)out_size;

    cudaFuncSetAttribute(lstm_mma_kernel, cudaFuncAttributeMaxDynamicSharedMemorySize, SMEM2);

    hinit_kernel<<<64, 256>>>();
    esplit_kernel<<<(int)(((size_t)ESZ + 255) / 256), 256>>>(emb);
    wsplit_kernel<<<(int)(((size_t)WSZ + 255) / 256), 256>>>(W);
    rsplit_kernel<<<(int)(((size_t)NCTA2 * 32 * 2048 + 255) / 256), 256>>>(Rm);
    dim3 g1(GDIM / 128, (SEQLEN * BATCH) / 64);
    xz_mma_kernel<<<g1, P1T>>>(bias, seq);
    lstm_mma_kernel<<<NCTA2, TPB2, SMEM2>>>(seq, (float*)d_out);
}

// round 16
// speedup vs baseline: 1.1240x; 1.1240x over previous
#include <cuda_runtime.h>
#include <cuda_bf16.h>
#include <math.h>
#include <stdint.h>

#define VOCAB   32000
#define EMBED   300
#define KPAD    304
#define HIDDEN  1024
#define BATCH   64
#define SEQLEN  512
#define GDIM    4096

#define NCTA2   128
#define TPB2    512

#define ESZ     (VOCAB * KPAD)
#define WSZ     (GDIM * KPAD)

// ---------------- device scratch ----------------
__device__ float          g_xz[(size_t)SEQLEN * BATCH * GDIM];
__device__ __nv_bfloat16  g_esplit[2 * ESZ];
__device__ __nv_bfloat16  g_wsplit[2 * WSZ];
__device__ __nv_bfloat16  g_hsplit[2][2 * 64 * 1024];
__device__ __nv_bfloat16  g_Rsplit[(size_t)NCTA2 * 32 * 2048];
__device__ unsigned       g_flags[NCTA2 * 8];      // 32B stride, own sector each
__device__ volatile unsigned g_bar_gen;            // persists across replays

// ---------------- flag-array grid barrier ----------------
// arrivals: plain release stores to private flags (no atomic serialization);
// leader CTA polls all flags with 127 threads in parallel, publishes gen.
__device__ __forceinline__ void grid_barrier(int cta, int tid, unsigned gen) {
    __syncthreads();
    if (cta == 0) {
        if (tid >= 1 && tid < NCTA2) {
            volatile unsigned* f = &g_flags[tid * 8];
            while (*f != gen) { }
            __threadfence();
        }
        __syncthreads();
        if (tid == 0) { __threadfence(); g_bar_gen = gen; }
    } else {
        if (tid == 0) {
            __threadfence();
            *(volatile unsigned*)&g_flags[cta * 8] = gen;
            while ((int)(g_bar_gen - gen) < 0) { }
            __threadfence();
        }
        __syncthreads();
    }
}

__device__ __forceinline__ void mma16816(float* d,
                                         uint32_t a0, uint32_t a1, uint32_t a2, uint32_t a3,
                                         uint32_t b0, uint32_t b1) {
    asm volatile("mma.sync.aligned.m16n8k16.row.col.f32.bf16.bf16.f32 "
        "{%0,%1,%2,%3}, {%4,%5,%6,%7}, {%8,%9}, {%0,%1,%2,%3};"
        : "+f"(d[0]), "+f"(d[1]), "+f"(d[2]), "+f"(d[3])
        : "r"(a0), "r"(a1), "r"(a2), "r"(a3), "r"(b0), "r"(b1));
}
__device__ __forceinline__ void ldsm4(uint32_t& r0, uint32_t& r1, uint32_t& r2, uint32_t& r3,
                                      uint32_t addr) {
    asm volatile("ldmatrix.sync.aligned.m8n8.x4.shared.b16 {%0,%1,%2,%3}, [%4];"
        : "=r"(r0), "=r"(r1), "=r"(r2), "=r"(r3) : "r"(addr));
}
__device__ __forceinline__ void cp16(uint32_t dst, const void* src) {
    asm volatile("cp.async.cg.shared.global [%0], [%1], 16;" :: "r"(dst), "l"(src));
}
#define CP_COMMIT() asm volatile("cp.async.commit_group;" ::: "memory")
#define CP_WAIT0()  asm volatile("cp.async.wait_group 0;" ::: "memory")
#define NBAR(id)    asm volatile("bar.sync %0, 64;" :: "r"(id) : "memory")

__device__ __forceinline__ uint32_t smem_to_u32(const void* p) {
    uint32_t a;
    asm("{ .reg .u64 t; cvta.to.shared.u64 t, %1; cvt.u32.u64 %0, t; }" : "=r"(a) : "l"(p));
    return a;
}

// =========================================================================
// Prologues
// =========================================================================
__global__ void hinit_kernel() {
    uint4 z = make_uint4(0, 0, 0, 0);
    int n4 = 2 * 2 * 64 * 1024 / 8;
    for (int i = blockIdx.x * blockDim.x + threadIdx.x; i < n4; i += gridDim.x * blockDim.x)
        ((uint4*)g_hsplit)[i] = z;
}

__global__ void esplit_kernel(const float* __restrict__ emb) {
    size_t i = (size_t)blockIdx.x * blockDim.x + threadIdx.x;
    if (i >= (size_t)ESZ) return;
    int k   = (int)(i % KPAD);
    int row = (int)(i / KPAD);
    float x = (k < EMBED) ? emb[(size_t)row * EMBED + k] : 0.f;
    __nv_bfloat16 hi = __float2bfloat16(x);
    g_esplit[i]       = hi;
    g_esplit[ESZ + i] = __float2bfloat16(x - __bfloat162float(hi));
}

__global__ void wsplit_kernel(const float* __restrict__ W) {
    size_t i = (size_t)blockIdx.x * blockDim.x + threadIdx.x;
    if (i >= (size_t)WSZ) return;
    int k = (int)(i % KPAD);
    int n = (int)(i / KPAD);
    float x = (k < EMBED) ? W[(size_t)k * GDIM + n] : 0.f;
    __nv_bfloat16 hi = __float2bfloat16(x);
    g_wsplit[i]       = hi;
    g_wsplit[WSZ + i] = __float2bfloat16(x - __bfloat162float(hi));
}

__global__ void rsplit_kernel(const float* __restrict__ Rm) {
    size_t i = (size_t)blockIdx.x * blockDim.x + threadIdx.x;
    if (i >= (size_t)NCTA2 * 32 * 2048) return;
    int k   = (int)(i & 2047);
    int n   = (int)((i >> 11) & 31);
    int cta = (int)(i >> 16);
    int col = (n >> 3) * 1024 + cta * 8 + (n & 7);
    int ks  = k & 1023;
    float x = Rm[(size_t)ks * GDIM + col];
    __nv_bfloat16 hi = __float2bfloat16(x);
    g_Rsplit[i] = (k < 1024) ? hi : __float2bfloat16(x - __bfloat162float(hi));
}

// =========================================================================
// Phase 1 (unchanged R14 winner): xz = emb[seq] @ W + bias on mma.sync
// =========================================================================
#define P1T     256
#define A_PL    (64 * 24)
#define W_PL    (128 * 24)

__global__ void __launch_bounds__(P1T) xz_mma_kernel(
    const float* __restrict__ bias, const int* __restrict__ seq)
{
    __shared__ __align__(16) __nv_bfloat16 Asm[2][2][A_PL];
    __shared__ __align__(16) __nv_bfloat16 Wsm[2][2][W_PL];
    __shared__ int toks[64];

    const int tid  = threadIdx.x;
    const int wid  = tid >> 5;
    const int lane = tid & 31;
    const int n0   = blockIdx.x * 128;
    const int m0   = blockIdx.y * 64;
    const int mt   = wid & 3;
    const int ntw  = (wid >> 2) & 1;

    if (tid < 64) {
        int m = m0 + tid;
        toks[tid] = seq[(m & 63) * SEQLEN + (m >> 6)];
    }
    __syncthreads();

    const uint32_t sbA0 = smem_to_u32(&Asm[0][0][0]);
    const uint32_t sbW0 = smem_to_u32(&Wsm[0][0][0]);
    const uint32_t ABUFB = 2 * A_PL * 2;
    const uint32_t WBUFB = 2 * W_PL * 2;

    const int aRowL = (lane & 7) + ((lane >> 3) & 1) * 8;
    const int aK8   = ((lane >> 4) & 1) * 8;
    const int bRowL = (lane & 7) + ((lane >> 4) & 1) * 8;
    const int bK8   = ((lane >> 3) & 1) * 8;
    const uint32_t aBase = sbA0 + (mt * 16 + aRowL) * 48 + aK8 * 2;
    const uint32_t wBase = sbW0 + (ntw * 64 + bRowL) * 48 + bK8 * 2;

    float acc[4][8];
    #pragma unroll
    for (int q = 0; q < 4; q++)
        #pragma unroll
        for (int i = 0; i < 8; i++) acc[q][i] = 0.f;

    {
        int u = tid;
        int pl = u >> 7, r = (u >> 1) & 63, c = u & 1;
        cp16(sbA0 + pl * (A_PL * 2) + r * 48 + c * 16,
             g_esplit + (size_t)pl * ESZ + (size_t)toks[r] * KPAD + c * 8);
        #pragma unroll
        for (int pass = 0; pass < 2; pass++) {
            int v = pass * P1T + tid;
            int wpl = v >> 8, wr = (v >> 1) & 127, wc = v & 1;
            cp16(sbW0 + wpl * (W_PL * 2) + wr * 48 + wc * 16,
                 g_wsplit + (size_t)wpl * WSZ + (size_t)(n0 + wr) * KPAD + wc * 8);
        }
        CP_COMMIT();
    }

    for (int s = 0; s < 19; s++) {
        CP_WAIT0();
        __syncthreads();
        if (s < 18) {
            const int k0 = (s + 1) * 16;
            const uint32_t ab = sbA0 + ((s + 1) & 1) * ABUFB;
            const uint32_t wb = sbW0 + ((s + 1) & 1) * WBUFB;
            int u = tid;
            int pl = u >> 7, r = (u >> 1) & 63, c = u & 1;
            cp16(ab + pl * (A_PL * 2) + r * 48 + c * 16,
                 g_esplit + (size_t)pl * ESZ + (size_t)toks[r] * KPAD + k0 + c * 8);
            #pragma unroll
            for (int pass = 0; pass < 2; pass++) {
                int v = pass * P1T + tid;
                int wpl = v >> 8, wr = (v >> 1) & 127, wc = v & 1;
                cp16(wb + wpl * (W_PL * 2) + wr * 48 + wc * 16,
                     g_wsplit + (size_t)wpl * WSZ + (size_t)(n0 + wr) * KPAD + k0 + wc * 8);
            }
            CP_COMMIT();
        }

        const uint32_t aB = aBase + (s & 1) * ABUFB;
        const uint32_t wB = wBase + (s & 1) * WBUFB;
        uint32_t ah0, ah1, ah2, ah3, al0, al1, al2, al3;
        ldsm4(ah0, ah1, ah2, ah3, aB);
        ldsm4(al0, al1, al2, al3, aB + A_PL * 2);
        #pragma unroll
        for (int q = 0; q < 4; q++) {
            uint32_t b0, b1, b2, b3;
            ldsm4(b0, b1, b2, b3, wB + q * 16 * 48);
            mma16816(acc[q],     ah0, ah1, ah2, ah3, b0, b1);
            mma16816(acc[q] + 4, ah0, ah1, ah2, ah3, b2, b3);
            mma16816(acc[q],     al0, al1, al2, al3, b0, b1);
            mma16816(acc[q] + 4, al0, al1, al2, al3, b2, b3);
            ldsm4(b0, b1, b2, b3, wB + W_PL * 2 + q * 16 * 48);
            mma16816(acc[q],     ah0, ah1, ah2, ah3, b0, b1);
            mma16816(acc[q] + 4, ah0, ah1, ah2, ah3, b2, b3);
        }
        __syncthreads();
    }

    {
        const int fg = lane >> 2, ft = lane & 3;
        const int row1 = m0 + mt * 16 + fg;
        #pragma unroll
        for (int q = 0; q < 4; q++) {
            #pragma unroll
            for (int pr = 0; pr < 2; pr++) {
                int col = n0 + ntw * 64 + q * 16 + pr * 8 + 2 * ft;
                float bx = __ldg(&bias[col]);
                float by = __ldg(&bias[col + 1]);
                *(float2*)&g_xz[(size_t)row1 * GDIM + col] =
                    make_float2(acc[q][pr * 4 + 0] + bx, acc[q][pr * 4 + 1] + by);
                *(float2*)&g_xz[(size_t)(row1 + 8) * GDIM + col] =
                    make_float2(acc[q][pr * 4 + 2] + bx, acc[q][pr * 4 + 3] + by);
            }
        }
    }
}

// =========================================================================
// Phase 2 v6: R14 structure (512 thr / 16 warps, decoupled groups) +
// register-level fragment double-buffering + flag-array grid barrier.
// =========================================================================
// smem layout (bytes)
#define SM_B     0          // 32 x 4112                     = 131,584
#define BSTR_B   4112
#define SM_A     131584     // 8 grp x 2 buf x 4352          = 69,632
#define AGRP     8704
#define ABUFSZ   4352
#define ASTR_B   272
#define SM_Z     201216     // 2 x 8448                      = 16,896
#define SMEM2    218112

__global__ void __launch_bounds__(TPB2, 1)
lstm_mma_kernel(const int* __restrict__ seq, float* __restrict__ out)
{
    extern __shared__ char smem[];
    const uint32_t sb = smem_to_u32(smem);
    const int tid   = threadIdx.x;
    const int wid   = tid >> 5;
    const int lane  = tid & 31;
    const int cta   = blockIdx.x;
    const int mt    = wid & 3;
    const int ntile = (wid >> 2) & 1;
    const int khalf = wid >> 3;
    const int grp   = mt + khalf * 4;
    const int nbid  = 1 + grp;
    const int m0    = mt * 16;
    const int nbase = ntile * 16;

    // ---- load resident B slice ----
    {
        const uint4* src = (const uint4*)(g_Rsplit + (size_t)cta * 32 * 2048);
        for (int idx = tid; idx < 32 * 256; idx += TPB2) {
            int r = idx >> 8, c = idx & 255;
            *(uint4*)(smem + SM_B + r * BSTR_B + c * 16) = src[r * 256 + c];
        }
    }

    const int gb = tid >> 3;
    const int gj = tid & 7;
    float c_r = 0.f, h_r = 0.f;

    const int aRowL = (lane & 7) + ((lane >> 3) & 1) * 8;
    const int aK8   = ((lane >> 4) & 1) * 8;
    const int bRow  = nbase + (lane & 7) + ((lane >> 4) & 1) * 8;
    const int bK8   = ((lane >> 3) & 1) * 8;
    const uint32_t aAddr0  = sb + SM_A + grp * AGRP + aRowL * ASTR_B + aK8 * 2;
    const uint32_t bAddr0  = sb + SM_B + bRow * BSTR_B + bK8 * 2;
    const uint32_t aStage0 = sb + SM_A + grp * AGRP;

    float* z0_s = (float*)(smem + SM_Z);
    float* z1_s = (float*)(smem + SM_Z + 8448);
    float* zw_s = khalf ? z1_s : z0_s;

    unsigned gen = g_bar_gen;          // stable: no writer active at entry
    gen++; grid_barrier(cta, tid, gen);

    int p = 0;
    for (int t = 0; t < SEQLEN; t++) {
        const __nv_bfloat16* hbase = g_hsplit[p];

        const float* xzr = g_xz + (size_t)t * (BATCH * GDIM) + (size_t)gb * GDIM + cta * 8 + gj;
        float xi = __ldcg(xzr);
        float xf = __ldcg(xzr + 1024);
        float xg = __ldcg(xzr + 2048);
        float xo = __ldcg(xzr + 3072);
        int   mv = __ldg(&seq[gb * SEQLEN + t]);

        float acc[8];
        #pragma unroll
        for (int i = 0; i < 8; i++) acc[i] = 0.f;

        // stage chunk 0 into buf 0
        {
            const __nv_bfloat16* pl = hbase;
            const int k0g = khalf * 128;
            #pragma unroll
            for (int pass = 0; pass < 4; pass++) {
                int u = pass * 64 + ntile * 32 + lane;
                int r = u >> 4, c = u & 15;
                cp16(aStage0 + r * ASTR_B + c * 16,
                     pl + (size_t)(m0 + r) * 1024 + k0g + c * 8);
            }
            CP_COMMIT();
        }

        for (int ci = 0; ci < 8; ci++) {
            CP_WAIT0();
            NBAR(nbid);
            if (ci < 7) {
                int cn = ci + 1;
                const __nv_bfloat16* pl = hbase + (cn < 4 ? 0 : 65536);
                const int k0g = (cn & 3) * 256 + khalf * 128;
                const uint32_t dst = aStage0 + (cn & 1) * ABUFSZ;
                #pragma unroll
                for (int pass = 0; pass < 4; pass++) {
                    int u = pass * 64 + ntile * 32 + lane;
                    int r = u >> 4, c = u & 15;
                    cp16(dst + r * ASTR_B + c * 16,
                         pl + (size_t)(m0 + r) * 1024 + k0g + c * 8);
                }
                CP_COMMIT();
            }

            const uint32_t aB = aAddr0 + (ci & 1) * ABUFSZ;
            const int k0 = (ci & 3) * 256 + khalf * 128;
            const bool isHi = (ci < 4);

            // ---- software-pipelined fragment loop (reg double-buffer) ----
            uint32_t a[2][4], bh[2][4], bl[2][4];
            ldsm4(a[0][0], a[0][1], a[0][2], a[0][3], aB);
            ldsm4(bh[0][0], bh[0][1], bh[0][2], bh[0][3], bAddr0 + k0 * 2);
            if (isHi)
                ldsm4(bl[0][0], bl[0][1], bl[0][2], bl[0][3], bAddr0 + (1024 + k0) * 2);
            #pragma unroll
            for (int ks = 0; ks < 8; ks++) {
                const int cur = ks & 1, nxt = cur ^ 1;
                if (ks < 7) {
                    const int kl = (ks + 1) * 16;
                    ldsm4(a[nxt][0], a[nxt][1], a[nxt][2], a[nxt][3], aB + kl * 2);
                    ldsm4(bh[nxt][0], bh[nxt][1], bh[nxt][2], bh[nxt][3],
                          bAddr0 + (k0 + kl) * 2);
                    if (isHi)
                        ldsm4(bl[nxt][0], bl[nxt][1], bl[nxt][2], bl[nxt][3],
                              bAddr0 + (1024 + k0 + kl) * 2);
                }
                mma16816(acc,     a[cur][0], a[cur][1], a[cur][2], a[cur][3],
                         bh[cur][0], bh[cur][1]);
                mma16816(acc + 4, a[cur][0], a[cur][1], a[cur][2], a[cur][3],
                         bh[cur][2], bh[cur][3]);
                if (isHi) {
                    mma16816(acc,     a[cur][0], a[cur][1], a[cur][2], a[cur][3],
                             bl[cur][0], bl[cur][1]);
                    mma16816(acc + 4, a[cur][0], a[cur][1], a[cur][2], a[cur][3],
                             bl[cur][2], bl[cur][3]);
                }
            }
        }

        // ---- park z tiles (one buffer per k-half) ----
        {
            const int fg = lane >> 2, ft = lane & 3;
            #pragma unroll
            for (int blk = 0; blk < 2; blk++) {
                int ncol = nbase + blk * 8 + 2 * ft;
                zw_s[(m0 + fg)     * 33 + ncol]     = acc[blk * 4 + 0];
                zw_s[(m0 + fg)     * 33 + ncol + 1] = acc[blk * 4 + 1];
                zw_s[(m0 + fg + 8) * 33 + ncol]     = acc[blk * 4 + 2];
                zw_s[(m0 + fg + 8) * 33 + ncol + 1] = acc[blk * 4 + 3];
            }
        }
        __syncthreads();

        // ---- gates ----
        {
            const bool msk = (mv != 0);
            const int  zb  = gb * 33 + gj;
            float zi = z0_s[zb]      + z1_s[zb]      + xi;
            float zf = z0_s[zb + 8]  + z1_s[zb + 8]  + xf;
            float zg = z0_s[zb + 16] + z1_s[zb + 16] + xg;
            float zo = z0_s[zb + 24] + z1_s[zb + 24] + xo;
            float ig  = 1.f / (1.f + __expf(-zi));
            float fgt = 1.f / (1.f + __expf(-zf));
            float gg  = tanhf(zg);
            float og  = 1.f / (1.f + __expf(-zo));
            float cn = fgt * c_r + ig * gg;
            float hn = og * tanhf(cn);
            if (msk) { c_r = cn; h_r = hn; }

            __nv_bfloat16 hi = __float2bfloat16(h_r);
            __nv_bfloat16 lo = __float2bfloat16(h_r - __bfloat162float(hi));
            __nv_bfloat16* hN = g_hsplit[p ^ 1];
            hN[(size_t)gb * 1024 + cta * 8 + gj]         = hi;
            hN[65536 + (size_t)gb * 1024 + cta * 8 + gj] = lo;
        }

        p ^= 1;
        gen++; grid_barrier(cta, tid, gen);
    }

    out[(size_t)gb * HIDDEN + cta * 8 + gj] = h_r;
}

// ---------------- launch ----------------
extern "C" void kernel_launch(void* const* d_in, const int* in_sizes, int n_in,
                              void* d_out, int out_size) {
    const float* emb  = nullptr;
    const float* W    = nullptr;
    const float* Rm   = nullptr;
    const float* bias = nullptr;
    const int*   seq  = nullptr;
    for (int i = 0; i < n_in; i++) {
        switch (in_sizes[i]) {
            case VOCAB * EMBED:  emb  = (const float*)d_in[i]; break;
            case EMBED * GDIM:   W    = (const float*)d_in[i]; break;
            case HIDDEN * GDIM:  Rm   = (const float*)d_in[i]; break;
            case GDIM:           bias = (const float*)d_in[i]; break;
            case BATCH * SEQLEN: seq  = (const int*)d_in[i];   break;
        }
    }
    (void)out_size;

    cudaFuncSetAttribute(lstm_mma_kernel, cudaFuncAttributeMaxDynamicSharedMemorySize, SMEM2);

    hinit_kernel<<<64, 256>>>();
    esplit_kernel<<<(int)(((size_t)ESZ + 255) / 256), 256>>>(emb);
    wsplit_kernel<<<(int)(((size_t)WSZ + 255) / 256), 256>>>(W);
    rsplit_kernel<<<(int)(((size_t)NCTA2 * 32 * 2048 + 255) / 256), 256>>>(Rm);
    dim3 g1(GDIM / 128, (SEQLEN * BATCH) / 64);
    xz_mma_kernel<<<g1, P1T>>>(bias, seq);
    lstm_mma_kernel<<<NCTA2, TPB2, SMEM2>>>(seq, (float*)d_out);
}